// round 8
// baseline (speedup 1.0000x reference)
#include <cuda_runtime.h>
#include <cuda_fp16.h>

#define NNODES 100000
#define CDIM   128
#define EDGES  3200000
#define NB_SCAN 391   // ceil(NNODES/256)

// Scratch (__device__ globals; no allocation allowed)
__device__ float  g_agg[(size_t)NNODES * CDIM];
__device__ float  g_h1 [(size_t)NNODES * CDIM];
__device__ float  g_h2 [(size_t)NNODES * CDIM];
__device__ float  g_t  [(size_t)NNODES * CDIM];
__device__ __half g_hh [(size_t)NNODES * CDIM];   // fp16 mirror for gathers
__device__ float  g_inv[NNODES];
__device__ int    g_deg[NNODES];
__device__ int    g_rowptr[NNODES + 1];
__device__ int    g_wcur[NNODES];
__device__ int    g_eidx[EDGES];
__device__ int    g_bsum[NB_SCAN];

// ---------------------------------------------------------------------------
// packed fp32x2 FMA (FFMA2) — tied operand must be %0 (naming it %3 ICEs nvcc)
__device__ __forceinline__ void ffma2(unsigned long long& d,
                                      unsigned long long a,
                                      unsigned long long b) {
    asm("fma.rn.f32x2 %0, %1, %2, %0;" : "+l"(d) : "l"(a), "l"(b));
}
__device__ __forceinline__ unsigned long long pack2(float v) {
    unsigned long long r;
    asm("mov.b64 %0, {%1, %1};" : "=l"(r) : "f"(v));
    return r;
}
union F2U { unsigned long long u; float2 f; };

__device__ __forceinline__ void add8(float* acc, uint4 u) {
    float2 a;
    a = __half22float2(*(__half2*)&u.x); acc[0] += a.x; acc[1] += a.y;
    a = __half22float2(*(__half2*)&u.y); acc[2] += a.x; acc[3] += a.y;
    a = __half22float2(*(__half2*)&u.z); acc[4] += a.x; acc[5] += a.y;
    a = __half22float2(*(__half2*)&u.w); acc[6] += a.x; acc[7] += a.y;
}

// ---------------------------------------------------------------------------
// CSR build step 1: degree histogram
__global__ void hist_kernel(const int* __restrict__ ei, int* __restrict__ deg) {
    int e = blockIdx.x * blockDim.x + threadIdx.x;
    if (e < EDGES) atomicAdd(deg + ei[EDGES + e], 1);
}

// step 2a: per-256-chunk partial sums
__global__ void partial_kernel(const int* __restrict__ deg, int* __restrict__ bsum) {
    int i = blockIdx.x * 256 + threadIdx.x;
    int v = (i < NNODES) ? deg[i] : 0;
#pragma unroll
    for (int off = 16; off > 0; off >>= 1)
        v += __shfl_down_sync(0xffffffffu, v, off);
    __shared__ int ws[8];
    int wid = threadIdx.x >> 5, lane = threadIdx.x & 31;
    if (lane == 0) ws[wid] = v;
    __syncthreads();
    if (wid == 0 && lane < 8) {
        int s = ws[lane];
#pragma unroll
        for (int off = 4; off > 0; off >>= 1)
            s += __shfl_down_sync(0x000000ffu, s, off);
        if (lane == 0) bsum[blockIdx.x] = s;
    }
}

// step 2b: exclusive scan of NB_SCAN block sums (single block, 512 threads)
__global__ void scanb_kernel(int* __restrict__ bsum) {
    int t = threadIdx.x;
    int v = (t < NB_SCAN) ? bsum[t] : 0;
    int x = v;
#pragma unroll
    for (int off = 1; off < 32; off <<= 1) {
        int y = __shfl_up_sync(0xffffffffu, x, off);
        if ((t & 31) >= off) x += y;
    }
    __shared__ int ws[16];
    int wid = t >> 5, lane = t & 31;
    if (lane == 31) ws[wid] = x;
    __syncthreads();
    if (wid == 0 && lane < 16) {
        int s = ws[lane];
#pragma unroll
        for (int off = 1; off < 16; off <<= 1) {
            int y = __shfl_up_sync(0x0000ffffu, s, off);
            if (lane >= off) s += y;
        }
        ws[lane] = s;
    }
    __syncthreads();
    int woff = (wid > 0) ? ws[wid - 1] : 0;
    if (t < NB_SCAN) bsum[t] = woff + x - v;   // exclusive
}

// step 2c: re-scan chunks with offsets -> rowptr
__global__ void rescan_kernel(const int* __restrict__ deg, const int* __restrict__ bsum,
                              int* __restrict__ rowptr) {
    int i = blockIdx.x * 256 + threadIdx.x;
    int v = (i < NNODES) ? deg[i] : 0;
    int x = v;
#pragma unroll
    for (int off = 1; off < 32; off <<= 1) {
        int y = __shfl_up_sync(0xffffffffu, x, off);
        if ((threadIdx.x & 31) >= off) x += y;
    }
    __shared__ int ws[8];
    int wid = threadIdx.x >> 5, lane = threadIdx.x & 31;
    if (lane == 31) ws[wid] = x;
    __syncthreads();
    if (wid == 0 && lane < 8) {
        int s = ws[lane];
#pragma unroll
        for (int off = 1; off < 8; off <<= 1) {
            int y = __shfl_up_sync(0x000000ffu, s, off);
            if (lane >= off) s += y;
        }
        ws[lane] = s;
    }
    __syncthreads();
    int woff = (wid > 0) ? ws[wid - 1] : 0;
    if (i < NNODES) rowptr[i] = bsum[blockIdx.x] + woff + x - v;
}

// step 3: init write cursors + inverse degree (+ rowptr[NNODES]=EDGES)
__global__ void initcur_kernel(const int* __restrict__ rowptr, const int* __restrict__ deg,
                               int* __restrict__ wcur, float* __restrict__ inv,
                               int* __restrict__ rowptr_end) {
    int n = blockIdx.x * blockDim.x + threadIdx.x;
    if (n == 0) *rowptr_end = EDGES;
    if (n < NNODES) {
        wcur[n] = rowptr[n];
        inv[n]  = 1.0f / fmaxf((float)deg[n], 1.0f);
    }
}

// step 4: fill CSR adjacency
__global__ void fill_kernel(const int* __restrict__ ei, int* __restrict__ wcur,
                            int* __restrict__ eidx) {
    int e = blockIdx.x * blockDim.x + threadIdx.x;
    if (e < EDGES) {
        int src = ei[e];
        int dst = ei[EDGES + e];
        int pos = atomicAdd(wcur + dst, 1);
        eidx[pos] = src;
    }
}

// ---------------------------------------------------------------------------
// fp32 -> fp16 mirror for x (only used once)
__global__ void tohalf_kernel(const float* __restrict__ in, __half* __restrict__ out) {
    long long i = (long long)blockIdx.x * blockDim.x + threadIdx.x;
    long long total = (long long)NNODES * CDIM / 8;
    if (i >= total) return;
    const float4* p = (const float4*)(in + i * 8);
    float4 a = p[0], b = p[1];
    __half2 h0 = __float22half2_rn(make_float2(a.x, a.y));
    __half2 h1 = __float22half2_rn(make_float2(a.z, a.w));
    __half2 h2 = __float22half2_rn(make_float2(b.x, b.y));
    __half2 h3 = __float22half2_rn(make_float2(b.z, b.w));
    uint4 v;
    v.x = *(unsigned*)&h0; v.y = *(unsigned*)&h1;
    v.z = *(unsigned*)&h2; v.w = *(unsigned*)&h3;
    *(uint4*)(out + i * 8) = v;
}

// ---------------------------------------------------------------------------
// Half-warp aggregate (128-wide rows): 16 lanes per node, 2 nodes per warp.
// Each lane: ONE uint4 (8 halves) load per edge. fp32 accumulate.
__global__ void aggregate128_kernel(const int* __restrict__ rowptr,
                                    const int* __restrict__ eidx,
                                    const __half* __restrict__ hh,
                                    const float* __restrict__ inv,
                                    float* __restrict__ out) {
    int gtid = blockIdx.x * blockDim.x + threadIdx.x;
    int node = (gtid >> 5) * 2 + ((threadIdx.x & 31) >> 4);
    int sub  = threadIdx.x & 15;
    if (node >= NNODES) return;
    int s = rowptr[node];
    int e = rowptr[node + 1];

    float acc[8];
#pragma unroll
    for (int v = 0; v < 8; v++) acc[v] = 0.f;

    int i = s;
    for (; i + 1 < e; i += 2) {
        int s0 = eidx[i], s1 = eidx[i + 1];
        uint4 u0 = *(const uint4*)(hh + (size_t)s0 * 128 + sub * 8);
        uint4 u1 = *(const uint4*)(hh + (size_t)s1 * 128 + sub * 8);
        add8(acc, u0);
        add8(acc, u1);
    }
    if (i < e) {
        uint4 u0 = *(const uint4*)(hh + (size_t)eidx[i] * 128 + sub * 8);
        add8(acc, u0);
    }

    float iv = inv[node];
    float* op = out + (size_t)node * 128 + sub * 8;
    *(float4*)op       = make_float4(acc[0]*iv, acc[1]*iv, acc[2]*iv, acc[3]*iv);
    *(float4*)(op + 4) = make_float4(acc[4]*iv, acc[5]*iv, acc[6]*iv, acc[7]*iv);
}

// Layer-3 fused aggregate (64-wide): 8 lanes per node, 4 nodes per warp.
// out[n,c] = mean(hh64) + t[n,64+c] + bl3[c]
__global__ void aggregate_final_kernel(const int* __restrict__ rowptr,
                                       const int* __restrict__ eidx,
                                       const __half* __restrict__ hh,   // N x 64
                                       const float* __restrict__ t,     // N x 128
                                       const float* __restrict__ bl,
                                       const float* __restrict__ inv,
                                       float* __restrict__ out) {
    int gtid = blockIdx.x * blockDim.x + threadIdx.x;
    int node = (gtid >> 5) * 4 + ((threadIdx.x & 31) >> 3);
    int sub  = threadIdx.x & 7;
    if (node >= NNODES) return;
    int s = rowptr[node];
    int e = rowptr[node + 1];

    float acc[8];
#pragma unroll
    for (int v = 0; v < 8; v++) acc[v] = 0.f;

    int i = s;
    for (; i + 1 < e; i += 2) {
        int s0 = eidx[i], s1 = eidx[i + 1];
        uint4 u0 = *(const uint4*)(hh + (size_t)s0 * 64 + sub * 8);
        uint4 u1 = *(const uint4*)(hh + (size_t)s1 * 64 + sub * 8);
        add8(acc, u0);
        add8(acc, u1);
    }
    if (i < e) {
        uint4 u0 = *(const uint4*)(hh + (size_t)eidx[i] * 64 + sub * 8);
        add8(acc, u0);
    }

    float iv = inv[node];
    const float* sp = t + (size_t)node * CDIM + 64 + sub * 8;
    float4 s0 = *(const float4*)sp;
    float4 s1 = *(const float4*)(sp + 4);
    float4 b0 = *(const float4*)(bl + sub * 8);
    float4 b1 = *(const float4*)(bl + sub * 8 + 4);
    float* op = out + (size_t)node * 64 + sub * 8;
    *(float4*)op = make_float4(acc[0]*iv + s0.x + b0.x, acc[1]*iv + s0.y + b0.y,
                               acc[2]*iv + s0.z + b0.z, acc[3]*iv + s0.w + b0.w);
    *(float4*)(op + 4) = make_float4(acc[4]*iv + s1.x + b1.x, acc[5]*iv + s1.y + b1.y,
                                     acc[6]*iv + s1.z + b1.z, acc[7]*iv + s1.w + b1.w);
}

// ---------------------------------------------------------------------------
// FFMA2 combine: out[n,c] = act( mean@Wl^T + bl + h@Wr^T ); also writes fp16
// mirror hhout (tight COUT-wide) for the next layer's gather.
template<int COUT, bool RELU, bool WRITEH>
__global__ __launch_bounds__(256)
void combine_kernel(const float* __restrict__ mean, const float* __restrict__ h,
                    const float* __restrict__ Wl, const float* __restrict__ bl,
                    const float* __restrict__ Wr, float* __restrict__ out,
                    __half* __restrict__ hhout) {
    constexpr int BM = 128, BK = 16;
    constexpr int TN = COUT / 16;

    __shared__ float As[BK][BM + 2];
    __shared__ float Bs[BK][COUT + 2];

    const int tid = threadIdx.x;
    const int m0  = blockIdx.x * BM;
    const int tm  = (tid >> 4) * 8;
    const int tc0 = (tid & 15);

    unsigned long long acc[4][TN];
#pragma unroll
    for (int i = 0; i < 4; i++)
#pragma unroll
        for (int j = 0; j < TN; j++) acc[i][j] = 0ull;

#pragma unroll
    for (int phase = 0; phase < 2; phase++) {
        const float* Asrc = phase ? h  : mean;
        const float* Bsrc = phase ? Wr : Wl;

        for (int kc = 0; kc < CDIM; kc += BK) {
            __syncthreads();
#pragma unroll
            for (int s = tid; s < BM * BK / 4; s += 256) {
                int m  = s >> 2;
                int kg = (s & 3) * 4;
                int node = m0 + m;
                float4 v = make_float4(0.f, 0.f, 0.f, 0.f);
                if (node < NNODES)
                    v = *(const float4*)(Asrc + (size_t)node * CDIM + kc + kg);
                As[kg + 0][m] = v.x; As[kg + 1][m] = v.y;
                As[kg + 2][m] = v.z; As[kg + 3][m] = v.w;
            }
#pragma unroll
            for (int s = tid; s < COUT * BK / 4; s += 256) {
                int c  = s >> 2;
                int kg = (s & 3) * 4;
                float4 v = *(const float4*)(Bsrc + (size_t)c * CDIM + kc + kg);
                Bs[kg + 0][c] = v.x; Bs[kg + 1][c] = v.y;
                Bs[kg + 2][c] = v.z; Bs[kg + 3][c] = v.w;
            }
            __syncthreads();

#pragma unroll
            for (int k = 0; k < BK; k++) {
                F2U ap[4];
#pragma unroll
                for (int i = 0; i < 4; i++)
                    ap[i].f = *(const float2*)&As[k][tm + 2 * i];
                unsigned long long bp[TN];
#pragma unroll
                for (int j = 0; j < TN; j++)
                    bp[j] = pack2(Bs[k][tc0 + 16 * j]);
#pragma unroll
                for (int i = 0; i < 4; i++)
#pragma unroll
                    for (int j = 0; j < TN; j++)
                        ffma2(acc[i][j], ap[i].u, bp[j]);
            }
        }
    }

#pragma unroll
    for (int i = 0; i < 4; i++) {
        int n0 = m0 + tm + 2 * i;
#pragma unroll
        for (int j = 0; j < TN; j++) {
            int c = tc0 + 16 * j;
            F2U r; r.u = acc[i][j];
            float v0 = r.f.x + bl[c];
            float v1 = r.f.y + bl[c];
            if (RELU) { v0 = fmaxf(v0, 0.f); v1 = fmaxf(v1, 0.f); }
            if (n0 < NNODES) {
                out[(size_t)n0 * COUT + c] = v0;
                if (WRITEH) hhout[(size_t)n0 * COUT + c] = __float2half(v0);
            }
            if (n0 + 1 < NNODES) {
                out[(size_t)(n0 + 1) * COUT + c] = v1;
                if (WRITEH) hhout[(size_t)(n0 + 1) * COUT + c] = __float2half(v1);
            }
        }
    }
}

// ---------------------------------------------------------------------------
// Layer-3 pre-projection (FFMA2): t[n,0:64]=h@Wl3^T, t[n,64:128]=h@Wr3^T.
// Also writes fp16 of cols [0,64) to hhout (tight 64-wide).
__global__ __launch_bounds__(256)
void proj_kernel(const float* __restrict__ h,
                 const float* __restrict__ Wl, const float* __restrict__ Wr,
                 float* __restrict__ t, __half* __restrict__ hhout) {
    constexpr int BM = 128, BK = 16, COUT = 128, TN = 8;

    __shared__ float As[BK][BM + 2];
    __shared__ float Bs[BK][COUT + 2];

    const int tid = threadIdx.x;
    const int m0  = blockIdx.x * BM;
    const int tm  = (tid >> 4) * 8;
    const int tc0 = (tid & 15);

    unsigned long long acc[4][TN];
#pragma unroll
    for (int i = 0; i < 4; i++)
#pragma unroll
        for (int j = 0; j < TN; j++) acc[i][j] = 0ull;

    for (int kc = 0; kc < CDIM; kc += BK) {
        __syncthreads();
#pragma unroll
        for (int s = tid; s < BM * BK / 4; s += 256) {
            int m  = s >> 2;
            int kg = (s & 3) * 4;
            int node = m0 + m;
            float4 v = make_float4(0.f, 0.f, 0.f, 0.f);
            if (node < NNODES)
                v = *(const float4*)(h + (size_t)node * CDIM + kc + kg);
            As[kg + 0][m] = v.x; As[kg + 1][m] = v.y;
            As[kg + 2][m] = v.z; As[kg + 3][m] = v.w;
        }
#pragma unroll
        for (int s = tid; s < COUT * BK / 4; s += 256) {
            int c  = s >> 2;
            int kg = (s & 3) * 4;
            const float* w = (c < 64) ? (Wl + (size_t)c * CDIM)
                                      : (Wr + (size_t)(c - 64) * CDIM);
            float4 v = *(const float4*)(w + kc + kg);
            Bs[kg + 0][c] = v.x; Bs[kg + 1][c] = v.y;
            Bs[kg + 2][c] = v.z; Bs[kg + 3][c] = v.w;
        }
        __syncthreads();

#pragma unroll
        for (int k = 0; k < BK; k++) {
            F2U ap[4];
#pragma unroll
            for (int i = 0; i < 4; i++)
                ap[i].f = *(const float2*)&As[k][tm + 2 * i];
            unsigned long long bp[TN];
#pragma unroll
            for (int j = 0; j < TN; j++)
                bp[j] = pack2(Bs[k][tc0 + 16 * j]);
#pragma unroll
            for (int i = 0; i < 4; i++)
#pragma unroll
                for (int j = 0; j < TN; j++)
                    ffma2(acc[i][j], ap[i].u, bp[j]);
        }
    }

#pragma unroll
    for (int i = 0; i < 4; i++) {
        int n0 = m0 + tm + 2 * i;
#pragma unroll
        for (int j = 0; j < TN; j++) {
            int c = tc0 + 16 * j;
            F2U r; r.u = acc[i][j];
            if (n0 < NNODES) {
                t[(size_t)n0 * COUT + c] = r.f.x;
                if (c < 64) hhout[(size_t)n0 * 64 + c] = __float2half(r.f.x);
            }
            if (n0 + 1 < NNODES) {
                t[(size_t)(n0 + 1) * COUT + c] = r.f.y;
                if (c < 64) hhout[(size_t)(n0 + 1) * 64 + c] = __float2half(r.f.y);
            }
        }
    }
}

// ---------------------------------------------------------------------------
extern "C" void kernel_launch(void* const* d_in, const int* in_sizes, int n_in,
                              void* d_out, int out_size) {
    const float* x   = (const float*)d_in[0];
    const int*   ei  = (const int*)d_in[1];      // int32 (JAX x64 disabled)
    const float* Wl1 = (const float*)d_in[2];
    const float* bl1 = (const float*)d_in[3];
    const float* Wr1 = (const float*)d_in[4];
    const float* Wl2 = (const float*)d_in[5];
    const float* bl2 = (const float*)d_in[6];
    const float* Wr2 = (const float*)d_in[7];
    const float* Wl3 = (const float*)d_in[8];
    const float* bl3 = (const float*)d_in[9];
    const float* Wr3 = (const float*)d_in[10];
    float* out = (float*)d_out;

    float *agg, *h1, *h2, *t, *inv;
    __half* hh;
    int *deg, *rowptr, *wcur, *eidx, *bsum;
    cudaGetSymbolAddress((void**)&agg, g_agg);
    cudaGetSymbolAddress((void**)&h1,  g_h1);
    cudaGetSymbolAddress((void**)&h2,  g_h2);
    cudaGetSymbolAddress((void**)&t,   g_t);
    cudaGetSymbolAddress((void**)&hh,  g_hh);
    cudaGetSymbolAddress((void**)&inv, g_inv);
    cudaGetSymbolAddress((void**)&deg, g_deg);
    cudaGetSymbolAddress((void**)&rowptr, g_rowptr);
    cudaGetSymbolAddress((void**)&wcur, g_wcur);
    cudaGetSymbolAddress((void**)&eidx, g_eidx);
    cudaGetSymbolAddress((void**)&bsum, g_bsum);

    const int eBlocks = (EDGES + 255) / 256;
    const int agg128Blocks = (NNODES * 16 + 255) / 256;   // 16 lanes per node
    const int agg64Blocks  = (NNODES * 8  + 255) / 256;   // 8 lanes per node
    const int combBlocks = (NNODES + 127) / 128;
    const int cvtBlocks = (int)(((long long)NNODES * CDIM / 8 + 255) / 256);

    // --- CSR build (once per launch) ---
    cudaMemsetAsync(deg, 0, NNODES * sizeof(int), 0);
    hist_kernel<<<eBlocks, 256>>>(ei, deg);
    partial_kernel<<<NB_SCAN, 256>>>(deg, bsum);
    scanb_kernel<<<1, 512>>>(bsum);
    rescan_kernel<<<NB_SCAN, 256>>>(deg, bsum, rowptr);
    initcur_kernel<<<NB_SCAN, 256>>>(rowptr, deg, wcur, inv, rowptr + NNODES);
    fill_kernel<<<eBlocks, 256>>>(ei, wcur, eidx);

    // --- Layer 1: x -> h1 (relu); h1 fp16 mirror written by combine ---
    tohalf_kernel<<<cvtBlocks, 256>>>(x, hh);
    aggregate128_kernel<<<agg128Blocks, 256>>>(rowptr, eidx, hh, inv, agg);
    combine_kernel<128, true, true><<<combBlocks, 256>>>(agg, x, Wl1, bl1, Wr1, h1, hh);

    // --- Layer 2: h1 -> h2 (relu); mirror via combine epilogue ---
    aggregate128_kernel<<<agg128Blocks, 256>>>(rowptr, eidx, hh, inv, agg);
    combine_kernel<128, true, true><<<combBlocks, 256>>>(agg, h1, Wl2, bl2, Wr2, h2, hh);

    // --- Layer 3 (pre-projected): t = h2@[Wl3;Wr3]^T; 64-wide fused aggregate ---
    proj_kernel<<<combBlocks, 256>>>(h2, Wl3, Wr3, t, hh);
    aggregate_final_kernel<<<agg64Blocks, 256>>>(rowptr, eidx, hh, t, bl3, inv, out);
}

// round 9
// speedup vs baseline: 1.4660x; 1.4660x over previous
#include <cuda_runtime.h>
#include <cuda_fp16.h>

#define NNODES 100000
#define CDIM   128
#define EDGES  3200000
#define NB_SCAN 391   // ceil(NNODES/256)

// Scratch (__device__ globals; no allocation allowed)
__device__ float  g_agg[(size_t)NNODES * CDIM];
__device__ float  g_h1 [(size_t)NNODES * CDIM];
__device__ float  g_h2 [(size_t)NNODES * CDIM];
__device__ float  g_t  [(size_t)NNODES * CDIM];
__device__ __half g_hh [(size_t)NNODES * CDIM];   // fp16 mirror for gathers
__device__ float  g_inv[NNODES];
__device__ int    g_deg[NNODES];
__device__ int    g_rowptr[NNODES + 1];
__device__ int    g_wcur[NNODES];
__device__ int    g_eidx[EDGES];
__device__ int    g_bsum[NB_SCAN];

// ---------------------------------------------------------------------------
// packed fp32x2 FMA (FFMA2) — tied operand must be %0 (naming it %3 ICEs nvcc)
__device__ __forceinline__ void ffma2(unsigned long long& d,
                                      unsigned long long a,
                                      unsigned long long b) {
    asm("fma.rn.f32x2 %0, %1, %2, %0;" : "+l"(d) : "l"(a), "l"(b));
}
__device__ __forceinline__ unsigned long long pack2(float v) {
    unsigned long long r;
    asm("mov.b64 %0, {%1, %1};" : "=l"(r) : "f"(v));
    return r;
}
union F2U { unsigned long long u; float2 f; };

__device__ __forceinline__ void add8(float* acc, uint4 u) {
    float2 a;
    a = __half22float2(*(__half2*)&u.x); acc[0] += a.x; acc[1] += a.y;
    a = __half22float2(*(__half2*)&u.y); acc[2] += a.x; acc[3] += a.y;
    a = __half22float2(*(__half2*)&u.z); acc[4] += a.x; acc[5] += a.y;
    a = __half22float2(*(__half2*)&u.w); acc[6] += a.x; acc[7] += a.y;
}

// ---------------------------------------------------------------------------
// CSR build step 1: degree histogram
__global__ void hist_kernel(const int* __restrict__ ei, int* __restrict__ deg) {
    int e = blockIdx.x * blockDim.x + threadIdx.x;
    if (e < EDGES) atomicAdd(deg + ei[EDGES + e], 1);
}

// step 2a: per-256-chunk partial sums
__global__ void partial_kernel(const int* __restrict__ deg, int* __restrict__ bsum) {
    int i = blockIdx.x * 256 + threadIdx.x;
    int v = (i < NNODES) ? deg[i] : 0;
#pragma unroll
    for (int off = 16; off > 0; off >>= 1)
        v += __shfl_down_sync(0xffffffffu, v, off);
    __shared__ int ws[8];
    int wid = threadIdx.x >> 5, lane = threadIdx.x & 31;
    if (lane == 0) ws[wid] = v;
    __syncthreads();
    if (wid == 0 && lane < 8) {
        int s = ws[lane];
#pragma unroll
        for (int off = 4; off > 0; off >>= 1)
            s += __shfl_down_sync(0x000000ffu, s, off);
        if (lane == 0) bsum[blockIdx.x] = s;
    }
}

// step 2b: exclusive scan of NB_SCAN block sums (single block, 512 threads)
__global__ void scanb_kernel(int* __restrict__ bsum) {
    int t = threadIdx.x;
    int v = (t < NB_SCAN) ? bsum[t] : 0;
    int x = v;
#pragma unroll
    for (int off = 1; off < 32; off <<= 1) {
        int y = __shfl_up_sync(0xffffffffu, x, off);
        if ((t & 31) >= off) x += y;
    }
    __shared__ int ws[16];
    int wid = t >> 5, lane = t & 31;
    if (lane == 31) ws[wid] = x;
    __syncthreads();
    if (wid == 0 && lane < 16) {
        int s = ws[lane];
#pragma unroll
        for (int off = 1; off < 16; off <<= 1) {
            int y = __shfl_up_sync(0x0000ffffu, s, off);
            if (lane >= off) s += y;
        }
        ws[lane] = s;
    }
    __syncthreads();
    int woff = (wid > 0) ? ws[wid - 1] : 0;
    if (t < NB_SCAN) bsum[t] = woff + x - v;   // exclusive
}

// step 2c: re-scan chunks with offsets -> rowptr
__global__ void rescan_kernel(const int* __restrict__ deg, const int* __restrict__ bsum,
                              int* __restrict__ rowptr) {
    int i = blockIdx.x * 256 + threadIdx.x;
    int v = (i < NNODES) ? deg[i] : 0;
    int x = v;
#pragma unroll
    for (int off = 1; off < 32; off <<= 1) {
        int y = __shfl_up_sync(0xffffffffu, x, off);
        if ((threadIdx.x & 31) >= off) x += y;
    }
    __shared__ int ws[8];
    int wid = threadIdx.x >> 5, lane = threadIdx.x & 31;
    if (lane == 31) ws[wid] = x;
    __syncthreads();
    if (wid == 0 && lane < 8) {
        int s = ws[lane];
#pragma unroll
        for (int off = 1; off < 8; off <<= 1) {
            int y = __shfl_up_sync(0x000000ffu, s, off);
            if (lane >= off) s += y;
        }
        ws[lane] = s;
    }
    __syncthreads();
    int woff = (wid > 0) ? ws[wid - 1] : 0;
    if (i < NNODES) rowptr[i] = bsum[blockIdx.x] + woff + x - v;
}

// step 3: init write cursors + inverse degree (+ rowptr[NNODES]=EDGES)
__global__ void initcur_kernel(const int* __restrict__ rowptr, const int* __restrict__ deg,
                               int* __restrict__ wcur, float* __restrict__ inv,
                               int* __restrict__ rowptr_end) {
    int n = blockIdx.x * blockDim.x + threadIdx.x;
    if (n == 0) *rowptr_end = EDGES;
    if (n < NNODES) {
        wcur[n] = rowptr[n];
        inv[n]  = 1.0f / fmaxf((float)deg[n], 1.0f);
    }
}

// step 4: fill CSR adjacency
__global__ void fill_kernel(const int* __restrict__ ei, int* __restrict__ wcur,
                            int* __restrict__ eidx) {
    int e = blockIdx.x * blockDim.x + threadIdx.x;
    if (e < EDGES) {
        int src = ei[e];
        int dst = ei[EDGES + e];
        int pos = atomicAdd(wcur + dst, 1);
        eidx[pos] = src;
    }
}

// ---------------------------------------------------------------------------
// fp32 -> fp16 mirror: first W cols (of stride S) per node, packed tight.
template<int W, int S>
__global__ void tohalf_kernel(const float* __restrict__ in, __half* __restrict__ out) {
    long long i = (long long)blockIdx.x * blockDim.x + threadIdx.x;
    long long total = (long long)NNODES * W / 8;
    if (i >= total) return;
    int n = (int)(i * 8 / W);
    int c = (int)(i * 8 % W);
    const float4* p = (const float4*)(in + (size_t)n * S + c);
    float4 a = p[0], b = p[1];
    __half2 h0 = __float22half2_rn(make_float2(a.x, a.y));
    __half2 h1 = __float22half2_rn(make_float2(a.z, a.w));
    __half2 h2 = __float22half2_rn(make_float2(b.x, b.y));
    __half2 h3 = __float22half2_rn(make_float2(b.z, b.w));
    uint4 v;
    v.x = *(unsigned*)&h0; v.y = *(unsigned*)&h1;
    v.z = *(unsigned*)&h2; v.w = *(unsigned*)&h3;
    *(uint4*)(out + (size_t)n * W + c) = v;
}

// ---------------------------------------------------------------------------
// Aggregate, 128-wide fp16 rows. WARP PER NODE; lanes split across EDGES:
// lanes 0-15 handle edge i, lanes 16-31 edge i+1 (one uint4 = 8 halves each).
// Final cross-half reduce via shfl_xor(16). fp32 accumulate, write fp32 mean.
__global__ void aggregate128_kernel(const int* __restrict__ rowptr,
                                    const int* __restrict__ eidx,
                                    const __half* __restrict__ hh,
                                    const float* __restrict__ inv,
                                    float* __restrict__ out) {
    int warp = (blockIdx.x * blockDim.x + threadIdx.x) >> 5;
    int lane = threadIdx.x & 31;
    int sub  = lane & 15;       // column group: 8 halves
    int half = lane >> 4;       // edge selector 0/1
    if (warp >= NNODES) return;
    int s = rowptr[warp];
    int e = rowptr[warp + 1];

    float acc[8];
#pragma unroll
    for (int v = 0; v < 8; v++) acc[v] = 0.f;

    int i = s;
    for (; i + 3 < e; i += 4) {           // 4 edges per iter, 2 loads per lane
        int s0 = eidx[i + half];
        int s1 = eidx[i + 2 + half];
        uint4 u0 = *(const uint4*)(hh + (size_t)s0 * 128 + sub * 8);
        uint4 u1 = *(const uint4*)(hh + (size_t)s1 * 128 + sub * 8);
        add8(acc, u0);
        add8(acc, u1);
    }
    for (; i + 1 < e; i += 2) {           // 2 edges
        int s0 = eidx[i + half];
        uint4 u0 = *(const uint4*)(hh + (size_t)s0 * 128 + sub * 8);
        add8(acc, u0);
    }
    if (i < e && half == 0) {             // last odd edge: lanes 0-15 only
        uint4 u0 = *(const uint4*)(hh + (size_t)eidx[i] * 128 + sub * 8);
        add8(acc, u0);
    }

    // combine the two edge-halves
#pragma unroll
    for (int v = 0; v < 8; v++)
        acc[v] += __shfl_xor_sync(0xffffffffu, acc[v], 16);

    if (half == 0) {
        float iv = inv[warp];
        float* op = out + (size_t)warp * 128 + sub * 8;
        *(float4*)op       = make_float4(acc[0]*iv, acc[1]*iv, acc[2]*iv, acc[3]*iv);
        *(float4*)(op + 4) = make_float4(acc[4]*iv, acc[5]*iv, acc[6]*iv, acc[7]*iv);
    }
}

// Layer-3 fused aggregate, 64-wide fp16 rows. WARP PER NODE; lanes split
// across 4 edges (lane>>3), 8 lanes per row (uint4 each).
// out[n,c] = mean + t[n,64+c] + bl3[c]
__global__ void aggregate_final_kernel(const int* __restrict__ rowptr,
                                       const int* __restrict__ eidx,
                                       const __half* __restrict__ hh,   // N x 64
                                       const float* __restrict__ t,     // N x 128
                                       const float* __restrict__ bl,
                                       const float* __restrict__ inv,
                                       float* __restrict__ out) {
    int warp = (blockIdx.x * blockDim.x + threadIdx.x) >> 5;
    int lane = threadIdx.x & 31;
    int sub  = lane & 7;        // column group: 8 halves
    int quad = lane >> 3;       // edge selector 0..3
    if (warp >= NNODES) return;
    int s = rowptr[warp];
    int e = rowptr[warp + 1];

    float acc[8];
#pragma unroll
    for (int v = 0; v < 8; v++) acc[v] = 0.f;

    int i = s;
    for (; i + 7 < e; i += 8) {           // 8 edges per iter, 2 loads per lane
        int s0 = eidx[i + quad];
        int s1 = eidx[i + 4 + quad];
        uint4 u0 = *(const uint4*)(hh + (size_t)s0 * 64 + sub * 8);
        uint4 u1 = *(const uint4*)(hh + (size_t)s1 * 64 + sub * 8);
        add8(acc, u0);
        add8(acc, u1);
    }
    for (; i + 3 < e; i += 4) {           // 4 edges
        int s0 = eidx[i + quad];
        uint4 u0 = *(const uint4*)(hh + (size_t)s0 * 64 + sub * 8);
        add8(acc, u0);
    }
    int rem = e - i;                      // 0..3 remaining
    if (quad < rem) {
        uint4 u0 = *(const uint4*)(hh + (size_t)eidx[i + quad] * 64 + sub * 8);
        add8(acc, u0);
    }

    // combine the four edge-quads
#pragma unroll
    for (int v = 0; v < 8; v++) {
        acc[v] += __shfl_xor_sync(0xffffffffu, acc[v], 8);
        acc[v] += __shfl_xor_sync(0xffffffffu, acc[v], 16);
    }

    if (quad == 0) {
        float iv = inv[warp];
        const float* sp = t + (size_t)warp * CDIM + 64 + sub * 8;
        float4 s0 = *(const float4*)sp;
        float4 s1 = *(const float4*)(sp + 4);
        float4 b0 = *(const float4*)(bl + sub * 8);
        float4 b1 = *(const float4*)(bl + sub * 8 + 4);
        float* op = out + (size_t)warp * 64 + sub * 8;
        *(float4*)op = make_float4(acc[0]*iv + s0.x + b0.x, acc[1]*iv + s0.y + b0.y,
                                   acc[2]*iv + s0.z + b0.z, acc[3]*iv + s0.w + b0.w);
        *(float4*)(op + 4) = make_float4(acc[4]*iv + s1.x + b1.x, acc[5]*iv + s1.y + b1.y,
                                         acc[6]*iv + s1.z + b1.z, acc[7]*iv + s1.w + b1.w);
    }
}

// ---------------------------------------------------------------------------
// FFMA2 combine: out[n,c] = act( mean@Wl^T + bl + h@Wr^T )
template<int COUT, bool RELU>
__global__ __launch_bounds__(256)
void combine_kernel(const float* __restrict__ mean, const float* __restrict__ h,
                    const float* __restrict__ Wl, const float* __restrict__ bl,
                    const float* __restrict__ Wr, float* __restrict__ out) {
    constexpr int BM = 128, BK = 16;
    constexpr int TN = COUT / 16;

    __shared__ float As[BK][BM + 2];
    __shared__ float Bs[BK][COUT + 2];

    const int tid = threadIdx.x;
    const int m0  = blockIdx.x * BM;
    const int tm  = (tid >> 4) * 8;
    const int tc0 = (tid & 15);

    unsigned long long acc[4][TN];
#pragma unroll
    for (int i = 0; i < 4; i++)
#pragma unroll
        for (int j = 0; j < TN; j++) acc[i][j] = 0ull;

#pragma unroll
    for (int phase = 0; phase < 2; phase++) {
        const float* Asrc = phase ? h  : mean;
        const float* Bsrc = phase ? Wr : Wl;

        for (int kc = 0; kc < CDIM; kc += BK) {
            __syncthreads();
#pragma unroll
            for (int s = tid; s < BM * BK / 4; s += 256) {
                int m  = s >> 2;
                int kg = (s & 3) * 4;
                int node = m0 + m;
                float4 v = make_float4(0.f, 0.f, 0.f, 0.f);
                if (node < NNODES)
                    v = *(const float4*)(Asrc + (size_t)node * CDIM + kc + kg);
                As[kg + 0][m] = v.x; As[kg + 1][m] = v.y;
                As[kg + 2][m] = v.z; As[kg + 3][m] = v.w;
            }
#pragma unroll
            for (int s = tid; s < COUT * BK / 4; s += 256) {
                int c  = s >> 2;
                int kg = (s & 3) * 4;
                float4 v = *(const float4*)(Bsrc + (size_t)c * CDIM + kc + kg);
                Bs[kg + 0][c] = v.x; Bs[kg + 1][c] = v.y;
                Bs[kg + 2][c] = v.z; Bs[kg + 3][c] = v.w;
            }
            __syncthreads();

#pragma unroll
            for (int k = 0; k < BK; k++) {
                F2U ap[4];
#pragma unroll
                for (int i = 0; i < 4; i++)
                    ap[i].f = *(const float2*)&As[k][tm + 2 * i];
                unsigned long long bp[TN];
#pragma unroll
                for (int j = 0; j < TN; j++)
                    bp[j] = pack2(Bs[k][tc0 + 16 * j]);
#pragma unroll
                for (int i = 0; i < 4; i++)
#pragma unroll
                    for (int j = 0; j < TN; j++)
                        ffma2(acc[i][j], ap[i].u, bp[j]);
            }
        }
    }

#pragma unroll
    for (int i = 0; i < 4; i++) {
        int n0 = m0 + tm + 2 * i;
#pragma unroll
        for (int j = 0; j < TN; j++) {
            int c = tc0 + 16 * j;
            F2U r; r.u = acc[i][j];
            float v0 = r.f.x + bl[c];
            float v1 = r.f.y + bl[c];
            if (RELU) { v0 = fmaxf(v0, 0.f); v1 = fmaxf(v1, 0.f); }
            if (n0 < NNODES)     out[(size_t)n0 * COUT + c]       = v0;
            if (n0 + 1 < NNODES) out[(size_t)(n0 + 1) * COUT + c] = v1;
        }
    }
}

// ---------------------------------------------------------------------------
// Layer-3 pre-projection (FFMA2): t[n,0:64]=h@Wl3^T, t[n,64:128]=h@Wr3^T
__global__ __launch_bounds__(256)
void proj_kernel(const float* __restrict__ h,
                 const float* __restrict__ Wl, const float* __restrict__ Wr,
                 float* __restrict__ t) {
    constexpr int BM = 128, BK = 16, COUT = 128, TN = 8;

    __shared__ float As[BK][BM + 2];
    __shared__ float Bs[BK][COUT + 2];

    const int tid = threadIdx.x;
    const int m0  = blockIdx.x * BM;
    const int tm  = (tid >> 4) * 8;
    const int tc0 = (tid & 15);

    unsigned long long acc[4][TN];
#pragma unroll
    for (int i = 0; i < 4; i++)
#pragma unroll
        for (int j = 0; j < TN; j++) acc[i][j] = 0ull;

    for (int kc = 0; kc < CDIM; kc += BK) {
        __syncthreads();
#pragma unroll
        for (int s = tid; s < BM * BK / 4; s += 256) {
            int m  = s >> 2;
            int kg = (s & 3) * 4;
            int node = m0 + m;
            float4 v = make_float4(0.f, 0.f, 0.f, 0.f);
            if (node < NNODES)
                v = *(const float4*)(h + (size_t)node * CDIM + kc + kg);
            As[kg + 0][m] = v.x; As[kg + 1][m] = v.y;
            As[kg + 2][m] = v.z; As[kg + 3][m] = v.w;
        }
#pragma unroll
        for (int s = tid; s < COUT * BK / 4; s += 256) {
            int c  = s >> 2;
            int kg = (s & 3) * 4;
            const float* w = (c < 64) ? (Wl + (size_t)c * CDIM)
                                      : (Wr + (size_t)(c - 64) * CDIM);
            float4 v = *(const float4*)(w + kc + kg);
            Bs[kg + 0][c] = v.x; Bs[kg + 1][c] = v.y;
            Bs[kg + 2][c] = v.z; Bs[kg + 3][c] = v.w;
        }
        __syncthreads();

#pragma unroll
        for (int k = 0; k < BK; k++) {
            F2U ap[4];
#pragma unroll
            for (int i = 0; i < 4; i++)
                ap[i].f = *(const float2*)&As[k][tm + 2 * i];
            unsigned long long bp[TN];
#pragma unroll
            for (int j = 0; j < TN; j++)
                bp[j] = pack2(Bs[k][tc0 + 16 * j]);
#pragma unroll
            for (int i = 0; i < 4; i++)
#pragma unroll
                for (int j = 0; j < TN; j++)
                    ffma2(acc[i][j], ap[i].u, bp[j]);
        }
    }

#pragma unroll
    for (int i = 0; i < 4; i++) {
        int n0 = m0 + tm + 2 * i;
#pragma unroll
        for (int j = 0; j < TN; j++) {
            int c = tc0 + 16 * j;
            F2U r; r.u = acc[i][j];
            if (n0 < NNODES)     t[(size_t)n0 * COUT + c]       = r.f.x;
            if (n0 + 1 < NNODES) t[(size_t)(n0 + 1) * COUT + c] = r.f.y;
        }
    }
}

// ---------------------------------------------------------------------------
extern "C" void kernel_launch(void* const* d_in, const int* in_sizes, int n_in,
                              void* d_out, int out_size) {
    const float* x   = (const float*)d_in[0];
    const int*   ei  = (const int*)d_in[1];      // int32 (JAX x64 disabled)
    const float* Wl1 = (const float*)d_in[2];
    const float* bl1 = (const float*)d_in[3];
    const float* Wr1 = (const float*)d_in[4];
    const float* Wl2 = (const float*)d_in[5];
    const float* bl2 = (const float*)d_in[6];
    const float* Wr2 = (const float*)d_in[7];
    const float* Wl3 = (const float*)d_in[8];
    const float* bl3 = (const float*)d_in[9];
    const float* Wr3 = (const float*)d_in[10];
    float* out = (float*)d_out;

    float *agg, *h1, *h2, *t, *inv;
    __half* hh;
    int *deg, *rowptr, *wcur, *eidx, *bsum;
    cudaGetSymbolAddress((void**)&agg, g_agg);
    cudaGetSymbolAddress((void**)&h1,  g_h1);
    cudaGetSymbolAddress((void**)&h2,  g_h2);
    cudaGetSymbolAddress((void**)&t,   g_t);
    cudaGetSymbolAddress((void**)&hh,  g_hh);
    cudaGetSymbolAddress((void**)&inv, g_inv);
    cudaGetSymbolAddress((void**)&deg, g_deg);
    cudaGetSymbolAddress((void**)&rowptr, g_rowptr);
    cudaGetSymbolAddress((void**)&wcur, g_wcur);
    cudaGetSymbolAddress((void**)&eidx, g_eidx);
    cudaGetSymbolAddress((void**)&bsum, g_bsum);

    const int eBlocks = (EDGES + 255) / 256;
    const int aggBlocks = (NNODES * 32 + 255) / 256;   // warp per node
    const int combBlocks = (NNODES + 127) / 128;
    const int cvt128Blocks = (int)(((long long)NNODES * 128 / 8 + 255) / 256);
    const int cvt64Blocks  = (int)(((long long)NNODES * 64  / 8 + 255) / 256);

    // --- CSR build (once per launch) ---
    cudaMemsetAsync(deg, 0, NNODES * sizeof(int), 0);
    hist_kernel<<<eBlocks, 256>>>(ei, deg);
    partial_kernel<<<NB_SCAN, 256>>>(deg, bsum);
    scanb_kernel<<<1, 512>>>(bsum);
    rescan_kernel<<<NB_SCAN, 256>>>(deg, bsum, rowptr);
    initcur_kernel<<<NB_SCAN, 256>>>(rowptr, deg, wcur, inv, rowptr + NNODES);
    fill_kernel<<<eBlocks, 256>>>(ei, wcur, eidx);

    // --- Layer 1: x -> h1 (relu) ---
    tohalf_kernel<128, 128><<<cvt128Blocks, 256>>>(x, hh);
    aggregate128_kernel<<<aggBlocks, 256>>>(rowptr, eidx, hh, inv, agg);
    combine_kernel<128, true><<<combBlocks, 256>>>(agg, x, Wl1, bl1, Wr1, h1);

    // --- Layer 2: h1 -> h2 (relu) ---
    tohalf_kernel<128, 128><<<cvt128Blocks, 256>>>(h1, hh);
    aggregate128_kernel<<<aggBlocks, 256>>>(rowptr, eidx, hh, inv, agg);
    combine_kernel<128, true><<<combBlocks, 256>>>(agg, h1, Wl2, bl2, Wr2, h2);

    // --- Layer 3 (pre-projected): t = h2@[Wl3;Wr3]^T; 64-wide fused aggregate ---
    proj_kernel<<<combBlocks, 256>>>(h2, Wl3, Wr3, t);
    tohalf_kernel<64, 128><<<cvt64Blocks, 256>>>(t, hh);
    aggregate_final_kernel<<<aggBlocks, 256>>>(rowptr, eidx, hh, t, bl3, inv, out);
}

// round 10
// speedup vs baseline: 2.5874x; 1.7649x over previous
#include <cuda_runtime.h>
#include <cuda_fp16.h>

#define NNODES 100000
#define CDIM   128
#define EDGES  3200000
#define NB_SCAN 391   // ceil(NNODES/256)

// Scratch (__device__ globals; no allocation allowed)
__device__ float  g_agg[(size_t)NNODES * CDIM];
__device__ float  g_h1 [(size_t)NNODES * CDIM];
__device__ float  g_h2 [(size_t)NNODES * CDIM];
__device__ float  g_t  [(size_t)NNODES * CDIM];
__device__ __half g_hh [(size_t)NNODES * CDIM];   // fp16 mirror for gathers
__device__ float  g_inv[NNODES];
__device__ int    g_deg[NNODES];
__device__ int    g_rowptr[NNODES + 1];
__device__ int    g_wcur[NNODES];
__device__ int    g_eidx[EDGES];
__device__ int    g_bsum[NB_SCAN];

// ---------------------------------------------------------------------------
// CSR build step 1: degree histogram
__global__ void hist_kernel(const int* __restrict__ ei, int* __restrict__ deg) {
    int e = blockIdx.x * blockDim.x + threadIdx.x;
    if (e < EDGES) atomicAdd(deg + ei[EDGES + e], 1);
}

// step 2a: per-256-chunk partial sums
__global__ void partial_kernel(const int* __restrict__ deg, int* __restrict__ bsum) {
    int i = blockIdx.x * 256 + threadIdx.x;
    int v = (i < NNODES) ? deg[i] : 0;
#pragma unroll
    for (int off = 16; off > 0; off >>= 1)
        v += __shfl_down_sync(0xffffffffu, v, off);
    __shared__ int ws[8];
    int wid = threadIdx.x >> 5, lane = threadIdx.x & 31;
    if (lane == 0) ws[wid] = v;
    __syncthreads();
    if (wid == 0 && lane < 8) {
        int s = ws[lane];
#pragma unroll
        for (int off = 4; off > 0; off >>= 1)
            s += __shfl_down_sync(0x000000ffu, s, off);
        if (lane == 0) bsum[blockIdx.x] = s;
    }
}

// step 2b: exclusive scan of NB_SCAN block sums (single block, 512 threads)
__global__ void scanb_kernel(int* __restrict__ bsum) {
    int t = threadIdx.x;
    int v = (t < NB_SCAN) ? bsum[t] : 0;
    int x = v;
#pragma unroll
    for (int off = 1; off < 32; off <<= 1) {
        int y = __shfl_up_sync(0xffffffffu, x, off);
        if ((t & 31) >= off) x += y;
    }
    __shared__ int ws[16];
    int wid = t >> 5, lane = t & 31;
    if (lane == 31) ws[wid] = x;
    __syncthreads();
    if (wid == 0 && lane < 16) {
        int s = ws[lane];
#pragma unroll
        for (int off = 1; off < 16; off <<= 1) {
            int y = __shfl_up_sync(0x0000ffffu, s, off);
            if (lane >= off) s += y;
        }
        ws[lane] = s;
    }
    __syncthreads();
    int woff = (wid > 0) ? ws[wid - 1] : 0;
    if (t < NB_SCAN) bsum[t] = woff + x - v;   // exclusive
}

// step 2c: re-scan chunks with offsets -> rowptr
__global__ void rescan_kernel(const int* __restrict__ deg, const int* __restrict__ bsum,
                              int* __restrict__ rowptr) {
    int i = blockIdx.x * 256 + threadIdx.x;
    int v = (i < NNODES) ? deg[i] : 0;
    int x = v;
#pragma unroll
    for (int off = 1; off < 32; off <<= 1) {
        int y = __shfl_up_sync(0xffffffffu, x, off);
        if ((threadIdx.x & 31) >= off) x += y;
    }
    __shared__ int ws[8];
    int wid = threadIdx.x >> 5, lane = threadIdx.x & 31;
    if (lane == 31) ws[wid] = x;
    __syncthreads();
    if (wid == 0 && lane < 8) {
        int s = ws[lane];
#pragma unroll
        for (int off = 1; off < 8; off <<= 1) {
            int y = __shfl_up_sync(0x000000ffu, s, off);
            if (lane >= off) s += y;
        }
        ws[lane] = s;
    }
    __syncthreads();
    int woff = (wid > 0) ? ws[wid - 1] : 0;
    if (i < NNODES) rowptr[i] = bsum[blockIdx.x] + woff + x - v;
}

// step 3: init write cursors + inverse degree (+ rowptr[NNODES]=EDGES)
__global__ void initcur_kernel(const int* __restrict__ rowptr, const int* __restrict__ deg,
                               int* __restrict__ wcur, float* __restrict__ inv,
                               int* __restrict__ rowptr_end) {
    int n = blockIdx.x * blockDim.x + threadIdx.x;
    if (n == 0) *rowptr_end = EDGES;
    if (n < NNODES) {
        wcur[n] = rowptr[n];
        inv[n]  = 1.0f / fmaxf((float)deg[n], 1.0f);
    }
}

// step 4: fill CSR adjacency
__global__ void fill_kernel(const int* __restrict__ ei, int* __restrict__ wcur,
                            int* __restrict__ eidx) {
    int e = blockIdx.x * blockDim.x + threadIdx.x;
    if (e < EDGES) {
        int src = ei[e];
        int dst = ei[EDGES + e];
        int pos = atomicAdd(wcur + dst, 1);
        eidx[pos] = src;
    }
}

// ---------------------------------------------------------------------------
// fp32 -> fp16 mirror: first W cols (of stride S) per node, packed tight.
template<int W, int S>
__global__ void tohalf_kernel(const float* __restrict__ in, __half* __restrict__ out) {
    long long i = (long long)blockIdx.x * blockDim.x + threadIdx.x;
    long long total = (long long)NNODES * W / 8;
    if (i >= total) return;
    int n = (int)(i * 8 / W);
    int c = (int)(i * 8 % W);
    const float4* p = (const float4*)(in + (size_t)n * S + c);
    float4 a = p[0], b = p[1];
    __half2 h0 = __float22half2_rn(make_float2(a.x, a.y));
    __half2 h1 = __float22half2_rn(make_float2(a.z, a.w));
    __half2 h2 = __float22half2_rn(make_float2(b.x, b.y));
    __half2 h3 = __float22half2_rn(make_float2(b.z, b.w));
    uint4 v;
    v.x = *(unsigned*)&h0; v.y = *(unsigned*)&h1;
    v.z = *(unsigned*)&h2; v.w = *(unsigned*)&h3;
    *(uint4*)(out + (size_t)n * W + c) = v;
}

// ---------------------------------------------------------------------------
// Gather-aggregate (fp16 gather, fp32 accumulate): warp per node (R7-best).
template<int W>
__global__ void aggregate_kernel(const int* __restrict__ rowptr,
                                 const int* __restrict__ eidx,
                                 const __half* __restrict__ hh,
                                 const float* __restrict__ inv,
                                 float* __restrict__ out) {
    constexpr int VEC = W / 32;                 // halves per lane: 4
    int warp = (blockIdx.x * blockDim.x + threadIdx.x) >> 5;
    int lane = threadIdx.x & 31;
    if (warp >= NNODES) return;
    int s = rowptr[warp];
    int e = rowptr[warp + 1];

    float acc[VEC];
#pragma unroll
    for (int v = 0; v < VEC; v++) acc[v] = 0.f;

    int i = s;
    for (; i + 3 < e; i += 4) {
        int s0 = eidx[i], s1 = eidx[i+1], s2 = eidx[i+2], s3 = eidx[i+3];
        uint2 u0 = *(const uint2*)(hh + (size_t)s0 * W + lane * 4);
        uint2 u1 = *(const uint2*)(hh + (size_t)s1 * W + lane * 4);
        uint2 u2 = *(const uint2*)(hh + (size_t)s2 * W + lane * 4);
        uint2 u3 = *(const uint2*)(hh + (size_t)s3 * W + lane * 4);
        float2 a, b;
        a = __half22float2(*(__half2*)&u0.x); acc[0] += a.x; acc[1] += a.y;
        b = __half22float2(*(__half2*)&u0.y); acc[2] += b.x; acc[3] += b.y;
        a = __half22float2(*(__half2*)&u1.x); acc[0] += a.x; acc[1] += a.y;
        b = __half22float2(*(__half2*)&u1.y); acc[2] += b.x; acc[3] += b.y;
        a = __half22float2(*(__half2*)&u2.x); acc[0] += a.x; acc[1] += a.y;
        b = __half22float2(*(__half2*)&u2.y); acc[2] += b.x; acc[3] += b.y;
        a = __half22float2(*(__half2*)&u3.x); acc[0] += a.x; acc[1] += a.y;
        b = __half22float2(*(__half2*)&u3.y); acc[2] += b.x; acc[3] += b.y;
    }
    for (; i < e; i++) {
        uint2 u0 = *(const uint2*)(hh + (size_t)eidx[i] * W + lane * 4);
        float2 a = __half22float2(*(__half2*)&u0.x);
        float2 b = __half22float2(*(__half2*)&u0.y);
        acc[0] += a.x; acc[1] += a.y; acc[2] += b.x; acc[3] += b.y;
    }

    float iv = inv[warp];
    float* op = out + (size_t)warp * W + lane * VEC;
    *(float4*)op = make_float4(acc[0]*iv, acc[1]*iv, acc[2]*iv, acc[3]*iv);
}

// Layer-3 fused aggregate: mean of hh(64-wide) + t[n,64+c] + bl3[c] -> out
__global__ void aggregate_final_kernel(const int* __restrict__ rowptr,
                                       const int* __restrict__ eidx,
                                       const __half* __restrict__ hh,   // N x 64
                                       const float* __restrict__ t,     // N x 128
                                       const float* __restrict__ bl,
                                       const float* __restrict__ inv,
                                       float* __restrict__ out) {
    int warp = (blockIdx.x * blockDim.x + threadIdx.x) >> 5;
    int lane = threadIdx.x & 31;
    if (warp >= NNODES) return;
    int s = rowptr[warp];
    int e = rowptr[warp + 1];

    float a0 = 0.f, a1 = 0.f;
    int i = s;
    for (; i + 3 < e; i += 4) {
        int s0 = eidx[i], s1 = eidx[i+1], s2 = eidx[i+2], s3 = eidx[i+3];
        unsigned u0 = *(const unsigned*)(hh + (size_t)s0 * 64 + lane * 2);
        unsigned u1 = *(const unsigned*)(hh + (size_t)s1 * 64 + lane * 2);
        unsigned u2 = *(const unsigned*)(hh + (size_t)s2 * 64 + lane * 2);
        unsigned u3 = *(const unsigned*)(hh + (size_t)s3 * 64 + lane * 2);
        float2 a;
        a = __half22float2(*(__half2*)&u0); a0 += a.x; a1 += a.y;
        a = __half22float2(*(__half2*)&u1); a0 += a.x; a1 += a.y;
        a = __half22float2(*(__half2*)&u2); a0 += a.x; a1 += a.y;
        a = __half22float2(*(__half2*)&u3); a0 += a.x; a1 += a.y;
    }
    for (; i < e; i++) {
        unsigned u0 = *(const unsigned*)(hh + (size_t)eidx[i] * 64 + lane * 2);
        float2 a = __half22float2(*(__half2*)&u0);
        a0 += a.x; a1 += a.y;
    }

    float iv = inv[warp];
    float2 self = *(const float2*)(t + (size_t)warp * CDIM + 64 + lane * 2);
    float2 bb   = *(const float2*)(bl + lane * 2);
    *(float2*)(out + (size_t)warp * 64 + lane * 2) =
        make_float2(a0 * iv + self.x + bb.x, a1 * iv + self.y + bb.y);
}

// ---------------------------------------------------------------------------
// Tensor-core GEMM pieces (mma.sync m16n8k16, fp16 in / fp32 accum)
#define MMA_16816(c, a, b) \
    asm volatile("mma.sync.aligned.m16n8k16.row.col.f32.f16.f16.f32 " \
        "{%0,%1,%2,%3}, {%4,%5,%6,%7}, {%8,%9}, {%0,%1,%2,%3};" \
        : "+f"((c)[0]), "+f"((c)[1]), "+f"((c)[2]), "+f"((c)[3]) \
        : "r"((a)[0]), "r"((a)[1]), "r"((a)[2]), "r"((a)[3]), \
          "r"((b)[0]), "r"((b)[1]))

__device__ __forceinline__ uint4 f8h8(float4 f0, float4 f1) {
    __half2 h0 = __float22half2_rn(make_float2(f0.x, f0.y));
    __half2 h1 = __float22half2_rn(make_float2(f0.z, f0.w));
    __half2 h2 = __float22half2_rn(make_float2(f1.x, f1.y));
    __half2 h3 = __float22half2_rn(make_float2(f1.z, f1.w));
    uint4 v;
    v.x = *(unsigned*)&h0; v.y = *(unsigned*)&h1;
    v.z = *(unsigned*)&h2; v.w = *(unsigned*)&h3;
    return v;
}

// combine: out[n,c] = act( mean@Wl^T + bl + h@Wr^T ), N=COUT=128, K=2x128
__global__ __launch_bounds__(256)
void combine_tc(const float* __restrict__ mean, const float* __restrict__ h,
                const float* __restrict__ Wl, const float* __restrict__ bl,
                const float* __restrict__ Wr, float* __restrict__ out) {
    constexpr int BM = 128, BN = 128, BK = 64, LD = 72;
    __shared__ __half As[BM][LD];
    __shared__ __half Bs[BN][LD];

    const int tid = threadIdx.x, wid = tid >> 5, lane = tid & 31;
    const int m0 = blockIdx.x * BM;
    const int wm = (wid & 3) * 32;
    const int wn = (wid >> 2) * 64;

    float acc[2][8][4];
#pragma unroll
    for (int i = 0; i < 2; i++)
#pragma unroll
        for (int j = 0; j < 8; j++)
#pragma unroll
            for (int d = 0; d < 4; d++) acc[i][j][d] = 0.f;

#pragma unroll
    for (int phase = 0; phase < 2; phase++) {
        const float* A = phase ? h  : mean;
        const float* B = phase ? Wr : Wl;
#pragma unroll
        for (int kc = 0; kc < CDIM; kc += BK) {
            __syncthreads();
#pragma unroll
            for (int s = tid; s < BM * BK / 8; s += 256) {
                int m = s >> 3, kg = (s & 7) * 8;
                uint4 v = make_uint4(0, 0, 0, 0);
                int node = m0 + m;
                if (node < NNODES) {
                    const float4* p = (const float4*)(A + (size_t)node * CDIM + kc + kg);
                    v = f8h8(p[0], p[1]);
                }
                *(uint4*)&As[m][kg] = v;
            }
#pragma unroll
            for (int s = tid; s < BN * BK / 8; s += 256) {
                int c = s >> 3, kg = (s & 7) * 8;
                const float4* p = (const float4*)(B + (size_t)c * CDIM + kc + kg);
                *(uint4*)&Bs[c][kg] = f8h8(p[0], p[1]);
            }
            __syncthreads();

#pragma unroll
            for (int ks = 0; ks < 4; ks++) {
                int k0 = ks * 16;
                unsigned a[2][4];
#pragma unroll
                for (int mf = 0; mf < 2; mf++) {
                    int row = wm + mf * 16 + (lane & 15);
                    int col = k0 + ((lane >> 4) << 3);
                    unsigned addr = (unsigned)__cvta_generic_to_shared(&As[row][col]);
                    asm volatile("ldmatrix.sync.aligned.m8n8.x4.shared.b16 {%0,%1,%2,%3}, [%4];"
                        : "=r"(a[mf][0]), "=r"(a[mf][1]), "=r"(a[mf][2]), "=r"(a[mf][3])
                        : "r"(addr));
                }
#pragma unroll
                for (int nf = 0; nf < 8; nf++) {
                    int l = lane & 15;
                    int rown = wn + nf * 8 + (l & 7);
                    int col = k0 + ((l >> 3) << 3);
                    unsigned addr = (unsigned)__cvta_generic_to_shared(&Bs[rown][col]);
                    unsigned b[2];
                    asm volatile("ldmatrix.sync.aligned.m8n8.x2.shared.b16 {%0,%1}, [%2];"
                        : "=r"(b[0]), "=r"(b[1]) : "r"(addr));
                    MMA_16816(acc[0][nf], a[0], b);
                    MMA_16816(acc[1][nf], a[1], b);
                }
            }
        }
    }

    const int tg = lane >> 2;          // row within fragment
    const int tc = (lane & 3) * 2;     // col pair
#pragma unroll
    for (int mf = 0; mf < 2; mf++) {
#pragma unroll
        for (int nf = 0; nf < 8; nf++) {
            int n_ = wn + nf * 8 + tc;
            float b0 = bl[n_], b1 = bl[n_ + 1];
            int mA = m0 + wm + mf * 16 + tg;
            int mB = mA + 8;
            if (mA < NNODES) {
                float v0 = fmaxf(acc[mf][nf][0] + b0, 0.f);
                float v1 = fmaxf(acc[mf][nf][1] + b1, 0.f);
                *(float2*)(out + (size_t)mA * BN + n_) = make_float2(v0, v1);
            }
            if (mB < NNODES) {
                float v0 = fmaxf(acc[mf][nf][2] + b0, 0.f);
                float v1 = fmaxf(acc[mf][nf][3] + b1, 0.f);
                *(float2*)(out + (size_t)mB * BN + n_) = make_float2(v0, v1);
            }
        }
    }
}

// proj: t[n,0:64] = h@Wl3^T, t[n,64:128] = h@Wr3^T   (no bias/relu, K=128)
__global__ __launch_bounds__(256)
void proj_tc(const float* __restrict__ h,
             const float* __restrict__ Wl, const float* __restrict__ Wr,
             float* __restrict__ t) {
    constexpr int BM = 128, BN = 128, BK = 64, LD = 72;
    __shared__ __half As[BM][LD];
    __shared__ __half Bs[BN][LD];

    const int tid = threadIdx.x, wid = tid >> 5, lane = tid & 31;
    const int m0 = blockIdx.x * BM;
    const int wm = (wid & 3) * 32;
    const int wn = (wid >> 2) * 64;

    float acc[2][8][4];
#pragma unroll
    for (int i = 0; i < 2; i++)
#pragma unroll
        for (int j = 0; j < 8; j++)
#pragma unroll
            for (int d = 0; d < 4; d++) acc[i][j][d] = 0.f;

#pragma unroll
    for (int kc = 0; kc < CDIM; kc += BK) {
        __syncthreads();
#pragma unroll
        for (int s = tid; s < BM * BK / 8; s += 256) {
            int m = s >> 3, kg = (s & 7) * 8;
            uint4 v = make_uint4(0, 0, 0, 0);
            int node = m0 + m;
            if (node < NNODES) {
                const float4* p = (const float4*)(h + (size_t)node * CDIM + kc + kg);
                v = f8h8(p[0], p[1]);
            }
            *(uint4*)&As[m][kg] = v;
        }
#pragma unroll
        for (int s = tid; s < BN * BK / 8; s += 256) {
            int c = s >> 3, kg = (s & 7) * 8;
            const float* w = (c < 64) ? (Wl + (size_t)c * CDIM)
                                      : (Wr + (size_t)(c - 64) * CDIM);
            const float4* p = (const float4*)(w + kc + kg);
            *(uint4*)&Bs[c][kg] = f8h8(p[0], p[1]);
        }
        __syncthreads();

#pragma unroll
        for (int ks = 0; ks < 4; ks++) {
            int k0 = ks * 16;
            unsigned a[2][4];
#pragma unroll
            for (int mf = 0; mf < 2; mf++) {
                int row = wm + mf * 16 + (lane & 15);
                int col = k0 + ((lane >> 4) << 3);
                unsigned addr = (unsigned)__cvta_generic_to_shared(&As[row][col]);
                asm volatile("ldmatrix.sync.aligned.m8n8.x4.shared.b16 {%0,%1,%2,%3}, [%4];"
                    : "=r"(a[mf][0]), "=r"(a[mf][1]), "=r"(a[mf][2]), "=r"(a[mf][3])
                    : "r"(addr));
            }
#pragma unroll
            for (int nf = 0; nf < 8; nf++) {
                int l = lane & 15;
                int rown = wn + nf * 8 + (l & 7);
                int col = k0 + ((l >> 3) << 3);
                unsigned addr = (unsigned)__cvta_generic_to_shared(&Bs[rown][col]);
                unsigned b[2];
                asm volatile("ldmatrix.sync.aligned.m8n8.x2.shared.b16 {%0,%1}, [%2];"
                    : "=r"(b[0]), "=r"(b[1]) : "r"(addr));
                MMA_16816(acc[0][nf], a[0], b);
                MMA_16816(acc[1][nf], a[1], b);
            }
        }
    }

    const int tg = lane >> 2;
    const int tc = (lane & 3) * 2;
#pragma unroll
    for (int mf = 0; mf < 2; mf++) {
#pragma unroll
        for (int nf = 0; nf < 8; nf++) {
            int n_ = wn + nf * 8 + tc;
            int mA = m0 + wm + mf * 16 + tg;
            int mB = mA + 8;
            if (mA < NNODES)
                *(float2*)(t + (size_t)mA * BN + n_) =
                    make_float2(acc[mf][nf][0], acc[mf][nf][1]);
            if (mB < NNODES)
                *(float2*)(t + (size_t)mB * BN + n_) =
                    make_float2(acc[mf][nf][2], acc[mf][nf][3]);
        }
    }
}

// ---------------------------------------------------------------------------
extern "C" void kernel_launch(void* const* d_in, const int* in_sizes, int n_in,
                              void* d_out, int out_size) {
    const float* x   = (const float*)d_in[0];
    const int*   ei  = (const int*)d_in[1];      // int32 (JAX x64 disabled)
    const float* Wl1 = (const float*)d_in[2];
    const float* bl1 = (const float*)d_in[3];
    const float* Wr1 = (const float*)d_in[4];
    const float* Wl2 = (const float*)d_in[5];
    const float* bl2 = (const float*)d_in[6];
    const float* Wr2 = (const float*)d_in[7];
    const float* Wl3 = (const float*)d_in[8];
    const float* bl3 = (const float*)d_in[9];
    const float* Wr3 = (const float*)d_in[10];
    float* out = (float*)d_out;

    float *agg, *h1, *h2, *t, *inv;
    __half* hh;
    int *deg, *rowptr, *wcur, *eidx, *bsum;
    cudaGetSymbolAddress((void**)&agg, g_agg);
    cudaGetSymbolAddress((void**)&h1,  g_h1);
    cudaGetSymbolAddress((void**)&h2,  g_h2);
    cudaGetSymbolAddress((void**)&t,   g_t);
    cudaGetSymbolAddress((void**)&hh,  g_hh);
    cudaGetSymbolAddress((void**)&inv, g_inv);
    cudaGetSymbolAddress((void**)&deg, g_deg);
    cudaGetSymbolAddress((void**)&rowptr, g_rowptr);
    cudaGetSymbolAddress((void**)&wcur, g_wcur);
    cudaGetSymbolAddress((void**)&eidx, g_eidx);
    cudaGetSymbolAddress((void**)&bsum, g_bsum);

    const int eBlocks = (EDGES + 255) / 256;
    const int aggBlocks = (NNODES * 32 + 255) / 256;   // warp per node
    const int combBlocks = (NNODES + 127) / 128;
    const int cvt128Blocks = (int)(((long long)NNODES * 128 / 8 + 255) / 256);
    const int cvt64Blocks  = (int)(((long long)NNODES * 64  / 8 + 255) / 256);

    // --- CSR build (once per launch) ---
    cudaMemsetAsync(deg, 0, NNODES * sizeof(int), 0);
    hist_kernel<<<eBlocks, 256>>>(ei, deg);
    partial_kernel<<<NB_SCAN, 256>>>(deg, bsum);
    scanb_kernel<<<1, 512>>>(bsum);
    rescan_kernel<<<NB_SCAN, 256>>>(deg, bsum, rowptr);
    initcur_kernel<<<NB_SCAN, 256>>>(rowptr, deg, wcur, inv, rowptr + NNODES);
    fill_kernel<<<eBlocks, 256>>>(ei, wcur, eidx);

    // --- Layer 1: x -> h1 (relu) ---
    tohalf_kernel<128, 128><<<cvt128Blocks, 256>>>(x, hh);
    aggregate_kernel<128><<<aggBlocks, 256>>>(rowptr, eidx, hh, inv, agg);
    combine_tc<<<combBlocks, 256>>>(agg, x, Wl1, bl1, Wr1, h1);

    // --- Layer 2: h1 -> h2 (relu) ---
    tohalf_kernel<128, 128><<<cvt128Blocks, 256>>>(h1, hh);
    aggregate_kernel<128><<<aggBlocks, 256>>>(rowptr, eidx, hh, inv, agg);
    combine_tc<<<combBlocks, 256>>>(agg, h1, Wl2, bl2, Wr2, h2);

    // --- Layer 3 (pre-projected): t = h2@[Wl3;Wr3]^T; 64-wide fused aggregate ---
    proj_tc<<<combBlocks, 256>>>(h2, Wl3, Wr3, t);
    tohalf_kernel<64, 128><<<cvt64Blocks, 256>>>(t, hh);
    aggregate_final_kernel<<<aggBlocks, 256>>>(rowptr, eidx, hh, t, bl3, inv, out);
}

// round 11
// speedup vs baseline: 2.8268x; 1.0925x over previous
#include <cuda_runtime.h>
#include <cuda_fp16.h>

#define NNODES 100000
#define CDIM   128
#define EDGES  3200000
#define NB_SCAN 391   // ceil(NNODES/256)

// Scratch (__device__ globals; no allocation allowed).
// Feature plane lives in fp16 (identical rounding to R10's tile-convert path).
__device__ __half g_xh  [(size_t)NNODES * CDIM];
__device__ __half g_aggh[(size_t)NNODES * CDIM];
__device__ __half g_h1h [(size_t)NNODES * CDIM];
__device__ __half g_h2h [(size_t)NNODES * CDIM];
__device__ __half g_th  [(size_t)NNODES * 64];    // proj cols 0..63 (fp16)
__device__ float  g_ts  [(size_t)NNODES * 64];    // proj cols 64..127 (fp32 self)
__device__ float  g_inv[NNODES];
__device__ int    g_deg[NNODES];
__device__ int    g_rowptr[NNODES + 1];
__device__ int    g_wcur[NNODES];
__device__ int    g_eidx[EDGES];
__device__ int    g_bsum[NB_SCAN];

// ---------------------------------------------------------------------------
// CSR build step 1: degree histogram
__global__ void hist_kernel(const int* __restrict__ ei, int* __restrict__ deg) {
    int e = blockIdx.x * blockDim.x + threadIdx.x;
    if (e < EDGES) atomicAdd(deg + ei[EDGES + e], 1);
}

// step 2a: per-256-chunk partial sums
__global__ void partial_kernel(const int* __restrict__ deg, int* __restrict__ bsum) {
    int i = blockIdx.x * 256 + threadIdx.x;
    int v = (i < NNODES) ? deg[i] : 0;
#pragma unroll
    for (int off = 16; off > 0; off >>= 1)
        v += __shfl_down_sync(0xffffffffu, v, off);
    __shared__ int ws[8];
    int wid = threadIdx.x >> 5, lane = threadIdx.x & 31;
    if (lane == 0) ws[wid] = v;
    __syncthreads();
    if (wid == 0 && lane < 8) {
        int s = ws[lane];
#pragma unroll
        for (int off = 4; off > 0; off >>= 1)
            s += __shfl_down_sync(0x000000ffu, s, off);
        if (lane == 0) bsum[blockIdx.x] = s;
    }
}

// step 2b: exclusive scan of NB_SCAN block sums (single block, 512 threads)
__global__ void scanb_kernel(int* __restrict__ bsum) {
    int t = threadIdx.x;
    int v = (t < NB_SCAN) ? bsum[t] : 0;
    int x = v;
#pragma unroll
    for (int off = 1; off < 32; off <<= 1) {
        int y = __shfl_up_sync(0xffffffffu, x, off);
        if ((t & 31) >= off) x += y;
    }
    __shared__ int ws[16];
    int wid = t >> 5, lane = t & 31;
    if (lane == 31) ws[wid] = x;
    __syncthreads();
    if (wid == 0 && lane < 16) {
        int s = ws[lane];
#pragma unroll
        for (int off = 1; off < 16; off <<= 1) {
            int y = __shfl_up_sync(0x0000ffffu, s, off);
            if (lane >= off) s += y;
        }
        ws[lane] = s;
    }
    __syncthreads();
    int woff = (wid > 0) ? ws[wid - 1] : 0;
    if (t < NB_SCAN) bsum[t] = woff + x - v;   // exclusive
}

// step 2c: re-scan chunks with offsets -> rowptr
__global__ void rescan_kernel(const int* __restrict__ deg, const int* __restrict__ bsum,
                              int* __restrict__ rowptr) {
    int i = blockIdx.x * 256 + threadIdx.x;
    int v = (i < NNODES) ? deg[i] : 0;
    int x = v;
#pragma unroll
    for (int off = 1; off < 32; off <<= 1) {
        int y = __shfl_up_sync(0xffffffffu, x, off);
        if ((threadIdx.x & 31) >= off) x += y;
    }
    __shared__ int ws[8];
    int wid = threadIdx.x >> 5, lane = threadIdx.x & 31;
    if (lane == 31) ws[wid] = x;
    __syncthreads();
    if (wid == 0 && lane < 8) {
        int s = ws[lane];
#pragma unroll
        for (int off = 1; off < 8; off <<= 1) {
            int y = __shfl_up_sync(0x000000ffu, s, off);
            if (lane >= off) s += y;
        }
        ws[lane] = s;
    }
    __syncthreads();
    int woff = (wid > 0) ? ws[wid - 1] : 0;
    if (i < NNODES) rowptr[i] = bsum[blockIdx.x] + woff + x - v;
}

// step 3: init write cursors + inverse degree (+ rowptr[NNODES]=EDGES)
__global__ void initcur_kernel(const int* __restrict__ rowptr, const int* __restrict__ deg,
                               int* __restrict__ wcur, float* __restrict__ inv,
                               int* __restrict__ rowptr_end) {
    int n = blockIdx.x * blockDim.x + threadIdx.x;
    if (n == 0) *rowptr_end = EDGES;
    if (n < NNODES) {
        wcur[n] = rowptr[n];
        inv[n]  = 1.0f / fmaxf((float)deg[n], 1.0f);
    }
}

// step 4: fill CSR adjacency
__global__ void fill_kernel(const int* __restrict__ ei, int* __restrict__ wcur,
                            int* __restrict__ eidx) {
    int e = blockIdx.x * blockDim.x + threadIdx.x;
    if (e < EDGES) {
        int src = ei[e];
        int dst = ei[EDGES + e];
        int pos = atomicAdd(wcur + dst, 1);
        eidx[pos] = src;
    }
}

// ---------------------------------------------------------------------------
// fp32 -> fp16 for x (once)
__global__ void tohalf_kernel(const float* __restrict__ in, __half* __restrict__ out) {
    long long i = (long long)blockIdx.x * blockDim.x + threadIdx.x;
    long long total = (long long)NNODES * CDIM / 8;
    if (i >= total) return;
    const float4* p = (const float4*)(in + i * 8);
    float4 a = p[0], b = p[1];
    __half2 h0 = __float22half2_rn(make_float2(a.x, a.y));
    __half2 h1 = __float22half2_rn(make_float2(a.z, a.w));
    __half2 h2 = __float22half2_rn(make_float2(b.x, b.y));
    __half2 h3 = __float22half2_rn(make_float2(b.z, b.w));
    uint4 v;
    v.x = *(unsigned*)&h0; v.y = *(unsigned*)&h1;
    v.z = *(unsigned*)&h2; v.w = *(unsigned*)&h3;
    *(uint4*)(out + i * 8) = v;
}

// ---------------------------------------------------------------------------
// Gather-aggregate (fp16 in, fp32 accumulate, fp16 mean out): warp per node.
__global__ void aggregate128_kernel(const int* __restrict__ rowptr,
                                    const int* __restrict__ eidx,
                                    const __half* __restrict__ hh,
                                    const float* __restrict__ inv,
                                    __half* __restrict__ out) {
    int warp = (blockIdx.x * blockDim.x + threadIdx.x) >> 5;
    int lane = threadIdx.x & 31;
    if (warp >= NNODES) return;
    int s = rowptr[warp];
    int e = rowptr[warp + 1];

    float acc[4] = {0.f, 0.f, 0.f, 0.f};

    int i = s;
    for (; i + 3 < e; i += 4) {
        int s0 = eidx[i], s1 = eidx[i+1], s2 = eidx[i+2], s3 = eidx[i+3];
        uint2 u0 = *(const uint2*)(hh + (size_t)s0 * 128 + lane * 4);
        uint2 u1 = *(const uint2*)(hh + (size_t)s1 * 128 + lane * 4);
        uint2 u2 = *(const uint2*)(hh + (size_t)s2 * 128 + lane * 4);
        uint2 u3 = *(const uint2*)(hh + (size_t)s3 * 128 + lane * 4);
        float2 a, b;
        a = __half22float2(*(__half2*)&u0.x); acc[0] += a.x; acc[1] += a.y;
        b = __half22float2(*(__half2*)&u0.y); acc[2] += b.x; acc[3] += b.y;
        a = __half22float2(*(__half2*)&u1.x); acc[0] += a.x; acc[1] += a.y;
        b = __half22float2(*(__half2*)&u1.y); acc[2] += b.x; acc[3] += b.y;
        a = __half22float2(*(__half2*)&u2.x); acc[0] += a.x; acc[1] += a.y;
        b = __half22float2(*(__half2*)&u2.y); acc[2] += b.x; acc[3] += b.y;
        a = __half22float2(*(__half2*)&u3.x); acc[0] += a.x; acc[1] += a.y;
        b = __half22float2(*(__half2*)&u3.y); acc[2] += b.x; acc[3] += b.y;
    }
    for (; i < e; i++) {
        uint2 u0 = *(const uint2*)(hh + (size_t)eidx[i] * 128 + lane * 4);
        float2 a = __half22float2(*(__half2*)&u0.x);
        float2 b = __half22float2(*(__half2*)&u0.y);
        acc[0] += a.x; acc[1] += a.y; acc[2] += b.x; acc[3] += b.y;
    }

    float iv = inv[warp];
    __half2 p0 = __float22half2_rn(make_float2(acc[0]*iv, acc[1]*iv));
    __half2 p1 = __float22half2_rn(make_float2(acc[2]*iv, acc[3]*iv));
    uint2 st;
    st.x = *(unsigned*)&p0; st.y = *(unsigned*)&p1;
    *(uint2*)(out + (size_t)warp * 128 + lane * 4) = st;
}

// Layer-3 fused aggregate: mean(th 64-wide) + ts[n,c] + bl3[c] -> out (fp32)
__global__ void aggregate_final_kernel(const int* __restrict__ rowptr,
                                       const int* __restrict__ eidx,
                                       const __half* __restrict__ th,   // N x 64
                                       const float* __restrict__ ts,    // N x 64
                                       const float* __restrict__ bl,
                                       const float* __restrict__ inv,
                                       float* __restrict__ out) {
    int warp = (blockIdx.x * blockDim.x + threadIdx.x) >> 5;
    int lane = threadIdx.x & 31;
    if (warp >= NNODES) return;
    int s = rowptr[warp];
    int e = rowptr[warp + 1];

    float a0 = 0.f, a1 = 0.f;
    int i = s;
    for (; i + 3 < e; i += 4) {
        int s0 = eidx[i], s1 = eidx[i+1], s2 = eidx[i+2], s3 = eidx[i+3];
        unsigned u0 = *(const unsigned*)(th + (size_t)s0 * 64 + lane * 2);
        unsigned u1 = *(const unsigned*)(th + (size_t)s1 * 64 + lane * 2);
        unsigned u2 = *(const unsigned*)(th + (size_t)s2 * 64 + lane * 2);
        unsigned u3 = *(const unsigned*)(th + (size_t)s3 * 64 + lane * 2);
        float2 a;
        a = __half22float2(*(__half2*)&u0); a0 += a.x; a1 += a.y;
        a = __half22float2(*(__half2*)&u1); a0 += a.x; a1 += a.y;
        a = __half22float2(*(__half2*)&u2); a0 += a.x; a1 += a.y;
        a = __half22float2(*(__half2*)&u3); a0 += a.x; a1 += a.y;
    }
    for (; i < e; i++) {
        unsigned u0 = *(const unsigned*)(th + (size_t)eidx[i] * 64 + lane * 2);
        float2 a = __half22float2(*(__half2*)&u0);
        a0 += a.x; a1 += a.y;
    }

    float iv = inv[warp];
    float2 self = *(const float2*)(ts + (size_t)warp * 64 + lane * 2);
    float2 bb   = *(const float2*)(bl + lane * 2);
    *(float2*)(out + (size_t)warp * 64 + lane * 2) =
        make_float2(a0 * iv + self.x + bb.x, a1 * iv + self.y + bb.y);
}

// ---------------------------------------------------------------------------
// Tensor-core GEMM pieces (mma.sync m16n8k16, fp16 in / fp32 accum)
#define MMA_16816(c, a, b) \
    asm volatile("mma.sync.aligned.m16n8k16.row.col.f32.f16.f16.f32 " \
        "{%0,%1,%2,%3}, {%4,%5,%6,%7}, {%8,%9}, {%0,%1,%2,%3};" \
        : "+f"((c)[0]), "+f"((c)[1]), "+f"((c)[2]), "+f"((c)[3]) \
        : "r"((a)[0]), "r"((a)[1]), "r"((a)[2]), "r"((a)[3]), \
          "r"((b)[0]), "r"((b)[1]))

__device__ __forceinline__ uint4 f8h8(float4 f0, float4 f1) {
    __half2 h0 = __float22half2_rn(make_float2(f0.x, f0.y));
    __half2 h1 = __float22half2_rn(make_float2(f0.z, f0.w));
    __half2 h2 = __float22half2_rn(make_float2(f1.x, f1.y));
    __half2 h3 = __float22half2_rn(make_float2(f1.z, f1.w));
    uint4 v;
    v.x = *(unsigned*)&h0; v.y = *(unsigned*)&h1;
    v.z = *(unsigned*)&h2; v.w = *(unsigned*)&h3;
    return v;
}

// combine: outh[n,c] = relu( mean@Wl^T + bl + h@Wr^T )  -> fp16, tight 128
// A sources are fp16 (mean tile + self tile), weights fp32 converted in-tile.
__global__ __launch_bounds__(256)
void combine_tc(const __half* __restrict__ mean, const __half* __restrict__ h,
                const float* __restrict__ Wl, const float* __restrict__ bl,
                const float* __restrict__ Wr, __half* __restrict__ outh) {
    constexpr int BM = 128, BN = 128, BK = 64, LD = 72;
    __shared__ __half As[BM][LD];
    __shared__ __half Bs[BN][LD];

    const int tid = threadIdx.x, wid = tid >> 5, lane = tid & 31;
    const int m0 = blockIdx.x * BM;
    const int wm = (wid & 3) * 32;
    const int wn = (wid >> 2) * 64;

    float acc[2][8][4];
#pragma unroll
    for (int i = 0; i < 2; i++)
#pragma unroll
        for (int j = 0; j < 8; j++)
#pragma unroll
            for (int d = 0; d < 4; d++) acc[i][j][d] = 0.f;

#pragma unroll
    for (int phase = 0; phase < 2; phase++) {
        const __half* A = phase ? h  : mean;
        const float*  B = phase ? Wr : Wl;
#pragma unroll
        for (int kc = 0; kc < CDIM; kc += BK) {
            __syncthreads();
#pragma unroll
            for (int s = tid; s < BM * BK / 8; s += 256) {
                int m = s >> 3, kg = (s & 7) * 8;
                uint4 v = make_uint4(0, 0, 0, 0);
                int node = m0 + m;
                if (node < NNODES)
                    v = *(const uint4*)(A + (size_t)node * CDIM + kc + kg);
                *(uint4*)&As[m][kg] = v;
            }
#pragma unroll
            for (int s = tid; s < BN * BK / 8; s += 256) {
                int c = s >> 3, kg = (s & 7) * 8;
                const float4* p = (const float4*)(B + (size_t)c * CDIM + kc + kg);
                *(uint4*)&Bs[c][kg] = f8h8(p[0], p[1]);
            }
            __syncthreads();

#pragma unroll
            for (int ks = 0; ks < 4; ks++) {
                int k0 = ks * 16;
                unsigned a[2][4];
#pragma unroll
                for (int mf = 0; mf < 2; mf++) {
                    int row = wm + mf * 16 + (lane & 15);
                    int col = k0 + ((lane >> 4) << 3);
                    unsigned addr = (unsigned)__cvta_generic_to_shared(&As[row][col]);
                    asm volatile("ldmatrix.sync.aligned.m8n8.x4.shared.b16 {%0,%1,%2,%3}, [%4];"
                        : "=r"(a[mf][0]), "=r"(a[mf][1]), "=r"(a[mf][2]), "=r"(a[mf][3])
                        : "r"(addr));
                }
#pragma unroll
                for (int nf = 0; nf < 8; nf++) {
                    int l = lane & 15;
                    int rown = wn + nf * 8 + (l & 7);
                    int col = k0 + ((l >> 3) << 3);
                    unsigned addr = (unsigned)__cvta_generic_to_shared(&Bs[rown][col]);
                    unsigned b[2];
                    asm volatile("ldmatrix.sync.aligned.m8n8.x2.shared.b16 {%0,%1}, [%2];"
                        : "=r"(b[0]), "=r"(b[1]) : "r"(addr));
                    MMA_16816(acc[0][nf], a[0], b);
                    MMA_16816(acc[1][nf], a[1], b);
                }
            }
        }
    }

    const int tg = lane >> 2;
    const int tc = (lane & 3) * 2;
#pragma unroll
    for (int mf = 0; mf < 2; mf++) {
#pragma unroll
        for (int nf = 0; nf < 8; nf++) {
            int n_ = wn + nf * 8 + tc;
            float b0 = bl[n_], b1 = bl[n_ + 1];
            int mA = m0 + wm + mf * 16 + tg;
            int mB = mA + 8;
            if (mA < NNODES) {
                __half2 hv = __float22half2_rn(make_float2(
                    fmaxf(acc[mf][nf][0] + b0, 0.f), fmaxf(acc[mf][nf][1] + b1, 0.f)));
                *(__half2*)(outh + (size_t)mA * BN + n_) = hv;
            }
            if (mB < NNODES) {
                __half2 hv = __float22half2_rn(make_float2(
                    fmaxf(acc[mf][nf][2] + b0, 0.f), fmaxf(acc[mf][nf][3] + b1, 0.f)));
                *(__half2*)(outh + (size_t)mB * BN + n_) = hv;
            }
        }
    }
}

// proj: cols 0..63 = h@Wl3^T -> th (fp16, tight 64); cols 64..127 = h@Wr3^T
// -> ts (fp32, tight 64). A source fp16.
__global__ __launch_bounds__(256)
void proj_tc(const __half* __restrict__ h,
             const float* __restrict__ Wl, const float* __restrict__ Wr,
             __half* __restrict__ th, float* __restrict__ ts) {
    constexpr int BM = 128, BN = 128, BK = 64, LD = 72;
    __shared__ __half As[BM][LD];
    __shared__ __half Bs[BN][LD];

    const int tid = threadIdx.x, wid = tid >> 5, lane = tid & 31;
    const int m0 = blockIdx.x * BM;
    const int wm = (wid & 3) * 32;
    const int wn = (wid >> 2) * 64;

    float acc[2][8][4];
#pragma unroll
    for (int i = 0; i < 2; i++)
#pragma unroll
        for (int j = 0; j < 8; j++)
#pragma unroll
            for (int d = 0; d < 4; d++) acc[i][j][d] = 0.f;

#pragma unroll
    for (int kc = 0; kc < CDIM; kc += BK) {
        __syncthreads();
#pragma unroll
        for (int s = tid; s < BM * BK / 8; s += 256) {
            int m = s >> 3, kg = (s & 7) * 8;
            uint4 v = make_uint4(0, 0, 0, 0);
            int node = m0 + m;
            if (node < NNODES)
                v = *(const uint4*)(h + (size_t)node * CDIM + kc + kg);
            *(uint4*)&As[m][kg] = v;
        }
#pragma unroll
        for (int s = tid; s < BN * BK / 8; s += 256) {
            int c = s >> 3, kg = (s & 7) * 8;
            const float* w = (c < 64) ? (Wl + (size_t)c * CDIM)
                                      : (Wr + (size_t)(c - 64) * CDIM);
            const float4* p = (const float4*)(w + kc + kg);
            *(uint4*)&Bs[c][kg] = f8h8(p[0], p[1]);
        }
        __syncthreads();

#pragma unroll
        for (int ks = 0; ks < 4; ks++) {
            int k0 = ks * 16;
            unsigned a[2][4];
#pragma unroll
            for (int mf = 0; mf < 2; mf++) {
                int row = wm + mf * 16 + (lane & 15);
                int col = k0 + ((lane >> 4) << 3);
                unsigned addr = (unsigned)__cvta_generic_to_shared(&As[row][col]);
                asm volatile("ldmatrix.sync.aligned.m8n8.x4.shared.b16 {%0,%1,%2,%3}, [%4];"
                    : "=r"(a[mf][0]), "=r"(a[mf][1]), "=r"(a[mf][2]), "=r"(a[mf][3])
                    : "r"(addr));
            }
#pragma unroll
            for (int nf = 0; nf < 8; nf++) {
                int l = lane & 15;
                int rown = wn + nf * 8 + (l & 7);
                int col = k0 + ((l >> 3) << 3);
                unsigned addr = (unsigned)__cvta_generic_to_shared(&Bs[rown][col]);
                unsigned b[2];
                asm volatile("ldmatrix.sync.aligned.m8n8.x2.shared.b16 {%0,%1}, [%2];"
                    : "=r"(b[0]), "=r"(b[1]) : "r"(addr));
                MMA_16816(acc[0][nf], a[0], b);
                MMA_16816(acc[1][nf], a[1], b);
            }
        }
    }

    const int tg = lane >> 2;
    const int tc = (lane & 3) * 2;
#pragma unroll
    for (int mf = 0; mf < 2; mf++) {
#pragma unroll
        for (int nf = 0; nf < 8; nf++) {
            int n_ = wn + nf * 8 + tc;
            int mA = m0 + wm + mf * 16 + tg;
            int mB = mA + 8;
            if (n_ < 64) {
                if (mA < NNODES)
                    *(__half2*)(th + (size_t)mA * 64 + n_) = __float22half2_rn(
                        make_float2(acc[mf][nf][0], acc[mf][nf][1]));
                if (mB < NNODES)
                    *(__half2*)(th + (size_t)mB * 64 + n_) = __float22half2_rn(
                        make_float2(acc[mf][nf][2], acc[mf][nf][3]));
            } else {
                int c = n_ - 64;
                if (mA < NNODES)
                    *(float2*)(ts + (size_t)mA * 64 + c) =
                        make_float2(acc[mf][nf][0], acc[mf][nf][1]);
                if (mB < NNODES)
                    *(float2*)(ts + (size_t)mB * 64 + c) =
                        make_float2(acc[mf][nf][2], acc[mf][nf][3]);
            }
        }
    }
}

// ---------------------------------------------------------------------------
extern "C" void kernel_launch(void* const* d_in, const int* in_sizes, int n_in,
                              void* d_out, int out_size) {
    const float* x   = (const float*)d_in[0];
    const int*   ei  = (const int*)d_in[1];      // int32 (JAX x64 disabled)
    const float* Wl1 = (const float*)d_in[2];
    const float* bl1 = (const float*)d_in[3];
    const float* Wr1 = (const float*)d_in[4];
    const float* Wl2 = (const float*)d_in[5];
    const float* bl2 = (const float*)d_in[6];
    const float* Wr2 = (const float*)d_in[7];
    const float* Wl3 = (const float*)d_in[8];
    const float* bl3 = (const float*)d_in[9];
    const float* Wr3 = (const float*)d_in[10];
    float* out = (float*)d_out;

    __half *xh, *aggh, *h1h, *h2h, *th;
    float *ts, *inv;
    int *deg, *rowptr, *wcur, *eidx, *bsum;
    cudaGetSymbolAddress((void**)&xh,   g_xh);
    cudaGetSymbolAddress((void**)&aggh, g_aggh);
    cudaGetSymbolAddress((void**)&h1h,  g_h1h);
    cudaGetSymbolAddress((void**)&h2h,  g_h2h);
    cudaGetSymbolAddress((void**)&th,   g_th);
    cudaGetSymbolAddress((void**)&ts,   g_ts);
    cudaGetSymbolAddress((void**)&inv,  g_inv);
    cudaGetSymbolAddress((void**)&deg,  g_deg);
    cudaGetSymbolAddress((void**)&rowptr, g_rowptr);
    cudaGetSymbolAddress((void**)&wcur, g_wcur);
    cudaGetSymbolAddress((void**)&eidx, g_eidx);
    cudaGetSymbolAddress((void**)&bsum, g_bsum);

    const int eBlocks = (EDGES + 255) / 256;
    const int aggBlocks = (NNODES * 32 + 255) / 256;   // warp per node
    const int combBlocks = (NNODES + 127) / 128;
    const int cvtBlocks = (int)(((long long)NNODES * CDIM / 8 + 255) / 256);

    // --- CSR build (once per launch) ---
    cudaMemsetAsync(deg, 0, NNODES * sizeof(int), 0);
    hist_kernel<<<eBlocks, 256>>>(ei, deg);
    partial_kernel<<<NB_SCAN, 256>>>(deg, bsum);
    scanb_kernel<<<1, 512>>>(bsum);
    rescan_kernel<<<NB_SCAN, 256>>>(deg, bsum, rowptr);
    initcur_kernel<<<NB_SCAN, 256>>>(rowptr, deg, wcur, inv, rowptr + NNODES);
    fill_kernel<<<eBlocks, 256>>>(ei, wcur, eidx);

    // --- Layer 1: x -> h1h (relu) ---
    tohalf_kernel<<<cvtBlocks, 256>>>(x, xh);
    aggregate128_kernel<<<aggBlocks, 256>>>(rowptr, eidx, xh, inv, aggh);
    combine_tc<<<combBlocks, 256>>>(aggh, xh, Wl1, bl1, Wr1, h1h);

    // --- Layer 2: h1h -> h2h (relu) ---
    aggregate128_kernel<<<aggBlocks, 256>>>(rowptr, eidx, h1h, inv, aggh);
    combine_tc<<<combBlocks, 256>>>(aggh, h1h, Wl2, bl2, Wr2, h2h);

    // --- Layer 3: proj (th fp16 / ts fp32), fused 64-wide aggregate ---
    proj_tc<<<combBlocks, 256>>>(h2h, Wl3, Wr3, th, ts);
    aggregate_final_kernel<<<aggBlocks, 256>>>(rowptr, eidx, th, ts, bl3, inv, out);
}